// round 14
// baseline (speedup 1.0000x reference)
#include <cuda_runtime.h>
#include <cuda_fp16.h>
#include <cstdint>

namespace {

constexpr int B = 2, N = 4096, D = 256, R = 64;
constexpr int TM = 64;         // n-rows per block == m-tile it produces
constexpr int TN = 64;         // m-tile
constexpr int THREADS = 512;   // 16 warps
constexpr int NTILES = N / TN; // 64

// smem layout in uint32 units; stride 36 (mod 32 == 4): conflict-free ldmatrix.
constexpr int STR = 36;
constexpr int OFE   = 0;                     // 64 x 36 (phase1: q_sm)
constexpr int OFK0  = OFE + 64 * STR;        // 64 x 36
constexpr int OFK1  = OFK0 + 64 * STR;
constexpr int OFV0  = OFK1 + 64 * STR;       // 256 x 36  (phase1: v_sm 64x260 here)
constexpr int OFV1  = OFV0 + 256 * STR;
constexpr int OFST0 = OFV1 + 256 * STR;      // 64 (floats)
constexpr int OFST1 = OFST0 + 64;
constexpr int OFRD  = OFST1 + 64;            // 256 (floats)
constexpr int SMEM_U32 = OFRD + 256;
constexpr int SMEM_BYTES = SMEM_U32 * 4;     // ~100.5 KB -> 1 block/SM, all resident

constexpr int VS = OFV0;                     // phase-1 val staging, stride 260

// fp16 pair-packed globals, natural pair order
__device__ uint32_t g_k[B * N * (R / 2)];
__device__ uint32_t g_vt[B * D * (N / 2)];   // [b][d][m-pair]

// producer/consumer gates (zero-initialized; reset at end of every run)
__device__ int g_ready[B * NTILES];
__device__ int g_done;

typedef unsigned long long ull;

__device__ __forceinline__ uint32_t pack_h2(float lo, float hi) {
    __half2 h = __floats2half2_rn(lo, hi);
    return *reinterpret_cast<uint32_t*>(&h);
}
__device__ __forceinline__ ull bcast2(float v) {
    ull r;
    asm("mov.b64 %0, {%1, %1};" : "=l"(r) : "f"(v));
    return r;
}
__device__ __forceinline__ void unpack2(ull v, float& lo, float& hi) {
    asm("mov.b64 {%0, %1}, %2;" : "=f"(lo), "=f"(hi) : "l"(v));
}
__device__ __forceinline__ void fma2(ull& d, ull a, ull b) {
    asm("fma.rn.f32x2 %0, %1, %2, %0;" : "+l"(d) : "l"(a), "l"(b));
}
__device__ __forceinline__ uint32_t smem_u32p(const void* p) {
    uint32_t a;
    asm("{ .reg .u64 t; cvta.to.shared.u64 t, %1; cvt.u32.u64 %0, t; }" : "=r"(a) : "l"(p));
    return a;
}
__device__ __forceinline__ void cp16(uint32_t dst, const void* src) {
    asm volatile("cp.async.cg.shared.global [%0], [%1], 16;" :: "r"(dst), "l"(src));
}
__device__ __forceinline__ void cp_commit() { asm volatile("cp.async.commit_group;"); }
__device__ __forceinline__ void cp_wait0()  { asm volatile("cp.async.wait_group 0;"); }
__device__ __forceinline__ int ld_acq(const int* p) {
    int v;
    asm volatile("ld.acquire.gpu.global.s32 %0, [%1];" : "=r"(v) : "l"(p));
    return v;
}
__device__ __forceinline__ void ldsm4(uint32_t& r0, uint32_t& r1, uint32_t& r2,
                                      uint32_t& r3, uint32_t addr) {
    asm volatile("ldmatrix.sync.aligned.m8n8.x4.shared.b16 {%0,%1,%2,%3}, [%4];"
                 : "=r"(r0), "=r"(r1), "=r"(r2), "=r"(r3) : "r"(addr));
}
__device__ __forceinline__ void mma_f16(float (&d)[4], const uint32_t (&a)[4],
                                        uint32_t b0, uint32_t b1) {
    asm volatile(
        "mma.sync.aligned.m16n8k16.row.col.f32.f16.f16.f32 "
        "{%0,%1,%2,%3}, {%4,%5,%6,%7}, {%8,%9}, {%0,%1,%2,%3};"
        : "+f"(d[0]), "+f"(d[1]), "+f"(d[2]), "+f"(d[3])
        : "r"(a[0]), "r"(a[1]), "r"(a[2]), "r"(a[3]), "r"(b0), "r"(b1));
}

// ---------------------------------------------------------------------------
// Fused kernel. Block (x, b): phase 1 produces q/k rows [64x,64x+64) and
// vt stripe m in [64x,64x+64); phase 2 = R12 prop body, m-loop starts at x.
// ---------------------------------------------------------------------------
__global__ void __launch_bounds__(THREADS) fused_kernel(const float* __restrict__ state,
                                                        const float* __restrict__ val,
                                                        const float* __restrict__ Wq,
                                                        const float* __restrict__ Wk,
                                                        float* __restrict__ out_ds,
                                                        float* __restrict__ out_dv) {
    extern __shared__ float smf[];
    uint32_t* sm = reinterpret_cast<uint32_t*>(smf);
    const uint32_t sbase = smem_u32p(smf);

    const int b  = blockIdx.y;
    const int x  = blockIdx.x;               // n-tile AND produced m-tile
    const int n0 = x * TM;
    const int t  = threadIdx.x;
    const int wid = t >> 5, lane = t & 31;
    const int g = lane >> 2, tg = lane & 3;
    const int wr = wid & 3, wc = wid >> 2;

    uint32_t* gk_b  = g_k + (size_t)b * N * 32;
    uint32_t* gvt_b = g_vt + (size_t)b * D * (N / 2);
    const float* st_b = state + (size_t)b * N;

    // ======================= PHASE 1: produce own unit =======================
    // Stage val rows [n0, n0+64): 64 x 256 floats at stride 260 (aligned 16B).
    {
        const float* srcv = val + ((size_t)b * N + n0) * D;
#pragma unroll
        for (int it = 0; it < 8; ++it) {
            int p = t + it * THREADS;        // 4096 float4
            int row = p >> 6, c4 = p & 63;
            cp16(sbase + (uint32_t)(VS + row * 260 + 4 * c4) * 4u, srcv + 4 * p);
        }
        cp_commit();
        cp_wait0();
        __syncthreads();
    }

    // q/k projection: col pair c = t&31, row group rg = t>>5 (rows 4rg..4rg+3).
    {
        const int c  = t & 31;
        const int rg = t >> 5;
        const ull* __restrict__ wqp = reinterpret_cast<const ull*>(Wq) + c;
        const ull* __restrict__ wkp = reinterpret_cast<const ull*>(Wk) + c;

        ull aq[4], ak[4];
#pragma unroll
        for (int j = 0; j < 4; ++j) { aq[j] = 0ull; ak[j] = 0ull; }

#pragma unroll 4
        for (int d = 0; d < D; ++d) {
            ull wq2 = __ldg(wqp + d * 32);
            ull wk2 = __ldg(wkp + d * 32);
#pragma unroll
            for (int j = 0; j < 4; ++j) {
                ull vb = bcast2(smf[VS + (rg * 4 + j) * 260 + d]);
                fma2(aq[j], vb, wq2);
                fma2(ak[j], vb, wk2);
            }
        }
#pragma unroll
        for (int j = 0; j < 4; ++j) {
            const int row = rg * 4 + j;
            float lo, hi;
            unpack2(aq[j], lo, hi);
            sm[OFE + row * STR + c] = pack_h2(lo, hi);        // q stays in smem
            unpack2(ak[j], lo, hi);
            gk_b[(size_t)(n0 + row) * 32 + c] = pack_h2(lo, hi);
        }
    }

    // vt stripe: g_vt[b][d][m-pair] for m in [n0, n0+64), all 256 d.
    {
#pragma unroll
        for (int it = 0; it < 8; ++it) {
            int p = t + it * THREADS;        // 4096 uint2 outputs
            int drow = p >> 4, j = p & 15;   // j: uint2 index (pairs 2j, 2j+1)
            uint2 o;
            o.x = pack_h2(smf[VS + (4 * j + 0) * 260 + drow],
                          smf[VS + (4 * j + 1) * 260 + drow]);
            o.y = pack_h2(smf[VS + (4 * j + 2) * 260 + drow],
                          smf[VS + (4 * j + 3) * 260 + drow]);
            *reinterpret_cast<uint2*>(&gvt_b[(size_t)drow * (N / 2) + 32 * x + 2 * j]) = o;
        }
    }

    __threadfence();
    __syncthreads();                 // all writes fenced by their own threads
    if (t == 0)
        atomicExch(&g_ready[b * NTILES + x], 1);   // publish (after all fences)

    // ---- Q A-fragments from smem (stride 36: conflict-free)
    uint32_t aqf[4][4];
    {
        const int r0 = OFE + (16 * wr + g) * STR;
        const int r1 = r0 + 8 * STR;
#pragma unroll
        for (int ks = 0; ks < 4; ++ks) {
            aqf[ks][0] = sm[r0 + 8 * ks + tg];
            aqf[ks][1] = sm[r1 + 8 * ks + tg];
            aqf[ks][2] = sm[r0 + 8 * ks + tg + 4];
            aqf[ks][3] = sm[r1 + 8 * ks + tg + 4];
        }
    }
    __syncthreads();                 // OFE now reusable as E buffer

    // ======================= PHASE 2: prop (R12 body) =======================
    auto prefetch = [&](int m0, int buf) {
        const int ofk  = buf ? OFK1 : OFK0;
        const int ofv  = buf ? OFV1 : OFV0;
        const int ofst = buf ? OFST1 : OFST0;
        {   // K tile: 64 rows x 8 uint4
            int row = t >> 3, cc = t & 7;
            cp16(sbase + (uint32_t)(ofk + row * STR + 4 * cc) * 4u,
                 gk_b + (size_t)(m0 + row) * 32 + 4 * cc);
        }
#pragma unroll
        for (int it = 0; it < 4; ++it) {   // VT: 256 rows x 8 uint4
            int p = t + it * THREADS;
            int row = p >> 3, cc = p & 7;
            cp16(sbase + (uint32_t)(ofv + row * STR + 4 * cc) * 4u,
                 gvt_b + (size_t)row * (N / 2) + m0 / 2 + 4 * cc);
        }
        if (t < 16)
            cp16(sbase + (uint32_t)(ofst + 4 * t) * 4u, st_b + m0 + 4 * t);
    };

    // own tile first (gate already set by this block)
    prefetch(n0, 0);
    cp_commit();

    // ldmatrix address components
    const int lrow = lane & 7;
    const int b1row = 16 * wc + 8 * (lane >> 4) + lrow;
    const int b1kb  = (lane >> 3) & 1;
    const int earow = 16 * wr + 8 * ((lane >> 3) & 1) + lrow;
    const int eakb  = lane >> 4;
    const int b2row = 64 * wc + 8 * (lane >> 4) + lrow;
    const int b2kb  = (lane >> 3) & 1;

    float dv[8][4];
#pragma unroll
    for (int nt = 0; nt < 8; ++nt)
#pragma unroll
        for (int j = 0; j < 4; ++j) dv[nt][j] = 0.f;
    float ds0 = 0.f, ds1 = 0.f;

#pragma unroll 1
    for (int i = 0; i < NTILES; ++i) {
        const int buf = i & 1;
        const int ofk  = buf ? OFK1 : OFK0;
        const int ofv  = buf ? OFV1 : OFV0;
        const int ofst = buf ? OFST1 : OFST0;

        cp_wait0();
        __syncthreads();

        if (i + 1 < NTILES) {
            const int nj = (x + i + 1) & (NTILES - 1);
            while (ld_acq(&g_ready[b * NTILES + nj]) == 0) {}
            prefetch(nj * TN, buf ^ 1);
            cp_commit();
        }

        // ---- MMA1: S(16x16 per warp) = Q . K^T
        float sacc[2][4];
#pragma unroll
        for (int nt = 0; nt < 2; ++nt)
#pragma unroll
            for (int j = 0; j < 4; ++j) sacc[nt][j] = 0.f;

#pragma unroll
        for (int ks = 0; ks < 4; ++ks) {
            uint32_t m0r, m1r, m2r, m3r;
            ldsm4(m0r, m1r, m2r, m3r,
                  sbase + (uint32_t)(ofk + b1row * STR + 8 * ks + 4 * b1kb) * 4u);
            mma_f16(sacc[0], aqf[ks], m0r, m1r);
            mma_f16(sacc[1], aqf[ks], m2r, m3r);
        }

        // ---- softsign + delta_state + E
#pragma unroll
        for (int nt = 0; nt < 2; ++nt) {
            const int c0 = 16 * wc + 8 * nt + 2 * tg;
            float e00 = __fdividef(sacc[nt][0], 1.f + fabsf(sacc[nt][0]));
            float e01 = __fdividef(sacc[nt][1], 1.f + fabsf(sacc[nt][1]));
            float e10 = __fdividef(sacc[nt][2], 1.f + fabsf(sacc[nt][2]));
            float e11 = __fdividef(sacc[nt][3], 1.f + fabsf(sacc[nt][3]));
            float s0 = smf[ofst + c0], s1 = smf[ofst + c0 + 1];
            ds0 = fmaf(e00, s0, fmaf(e01, s1, ds0));
            ds1 = fmaf(e10, s0, fmaf(e11, s1, ds1));
            const int es = 8 * wc + 4 * nt + tg;
            sm[OFE + (16 * wr + g) * STR + es]     = pack_h2(e00, e01);
            sm[OFE + (16 * wr + g + 8) * STR + es] = pack_h2(e10, e11);
        }
        __syncthreads();

        // ---- MMA2: DV(16x64 per warp) += E . V
#pragma unroll
        for (int ks = 0; ks < 4; ++ks) {
            uint32_t a[4];
            ldsm4(a[0], a[1], a[2], a[3],
                  sbase + (uint32_t)(OFE + earow * STR + 8 * ks + 4 * eakb) * 4u);
#pragma unroll
            for (int ntp = 0; ntp < 4; ++ntp) {
                uint32_t v0, v1, v2, v3;
                ldsm4(v0, v1, v2, v3,
                      sbase + (uint32_t)(ofv + (b2row + 16 * ntp) * STR
                                         + 8 * ks + 4 * b2kb) * 4u);
                mma_f16(dv[2 * ntp],     a, v0, v1);
                mma_f16(dv[2 * ntp + 1], a, v2, v3);
            }
        }
    }

    // ---- epilogue: DV writes
    {
        const int rowA = n0 + 16 * wr + g;
        float* dA = out_dv + ((size_t)b * N + rowA) * D;
        float* dB = dA + 8 * D;
#pragma unroll
        for (int nt = 0; nt < 8; ++nt) {
            const int col = 64 * wc + 8 * nt + 2 * tg;
            *reinterpret_cast<float2*>(dA + col) = make_float2(dv[nt][0], dv[nt][1]);
            *reinterpret_cast<float2*>(dB + col) = make_float2(dv[nt][2], dv[nt][3]);
        }
    }

    // ---- delta_state reduction
    ds0 += __shfl_xor_sync(0xFFFFFFFF, ds0, 1);
    ds0 += __shfl_xor_sync(0xFFFFFFFF, ds0, 2);
    ds1 += __shfl_xor_sync(0xFFFFFFFF, ds1, 1);
    ds1 += __shfl_xor_sync(0xFFFFFFFF, ds1, 2);
    __syncthreads();
    if (tg == 0) {
        smf[OFRD + (16 * wr + g) * 4 + wc]     = ds0;
        smf[OFRD + (16 * wr + g + 8) * 4 + wc] = ds1;
    }
    __syncthreads();
    if (t < TM)
        out_ds[b * N + n0 + t] = (smf[OFRD + t * 4] + smf[OFRD + t * 4 + 1]) +
                                 (smf[OFRD + t * 4 + 2] + smf[OFRD + t * 4 + 3]);

    // ---- gate reset for next graph replay (last block out resets everything)
    __syncthreads();
    if (t == 0) {
        int old = atomicAdd(&g_done, 1);
        if (old == B * NTILES - 1) {
            for (int j = 0; j < B * NTILES; ++j) g_ready[j] = 0;
            g_done = 0;
            __threadfence();
        }
    }
}

}  // namespace

extern "C" void kernel_launch(void* const* d_in, const int* in_sizes, int n_in,
                              void* d_out, int out_size) {
    const float* state = (const float*)d_in[0];   // [B, N]
    const float* val   = (const float*)d_in[1];   // [B, N, D]
    const float* Wq    = (const float*)d_in[2];   // [D, R]
    const float* Wk    = (const float*)d_in[3];   // [D, R]

    float* out_ds = (float*)d_out;                // [B, N]
    float* out_dv = out_ds + B * N;               // [B, N, D]

    cudaFuncSetAttribute(fused_kernel, cudaFuncAttributeMaxDynamicSharedMemorySize, SMEM_BYTES);

    fused_kernel<<<dim3(N / TM, B), THREADS, SMEM_BYTES>>>(state, val, Wq, Wk,
                                                           out_ds, out_dv);
}

// round 15
// speedup vs baseline: 1.2455x; 1.2455x over previous
#include <cuda_runtime.h>
#include <cuda_fp16.h>
#include <cstdint>

namespace {

constexpr int B = 2, N = 4096, D = 256, R = 64;
constexpr int TM = 64;         // n-rows per block
constexpr int TN = 64;         // m-tile
constexpr int THREADS = 512;   // 16 warps

// ---- prop smem layout in uint32 units; stride 40 (mod 32 == 8) conflict-free.
constexpr int OFE   = 0;                     // 64 x 40 (32 pair-cols used)
constexpr int OFK0  = OFE + 64 * 40;         // 64 x 40
constexpr int OFK1  = OFK0 + 64 * 40;
constexpr int OFV0  = OFK1 + 64 * 40;        // 256 x 40
constexpr int OFV1  = OFV0 + 256 * 40;
constexpr int OFST0 = OFV1 + 256 * 40;       // 64 (floats)
constexpr int OFST1 = OFST0 + 64;
constexpr int OFRD  = OFST1 + 64;            // 256 (floats)
constexpr int SMEM_U32 = OFRD + 256;
constexpr int SMEM_BYTES = SMEM_U32 * 4;     // ~111.6 KB

// ---- prep smem layout (floats): v tile + one 128-d W chunk (q and k)
constexpr int PVS  = 0;                      // 64 rows x 260 (val, fp32)
constexpr int PWQ  = PVS + 64 * 260;         // 128 x 64
constexpr int PWK  = PWQ + 128 * 64;         // 128 x 64
constexpr int PREP_FLOATS = PWK + 128 * 64;  // 33024
constexpr int PREP_SMEM = PREP_FLOATS * 4;   // 132096 B

// fp16 pair-packed globals (uint32 = half2), kslot-permuted (matches R10 prop)
__device__ uint32_t g_q[B * N * (R / 2)];
__device__ uint32_t g_k[B * N * (R / 2)];
__device__ uint32_t g_vt[B * D * (N / 2)];   // [b][d][m-pair], permuted

typedef unsigned long long ull;

// per-8-pair-group slot permutation: pair l -> slot (l&3)*2 + (l>>2)
__host__ __device__ __forceinline__ int kslot(int p) {
    return (p & ~7) | (((p & 3) << 1) | ((p & 7) >> 2));
}

__device__ __forceinline__ uint32_t pack_h2(float lo, float hi) {
    __half2 h = __floats2half2_rn(lo, hi);
    return *reinterpret_cast<uint32_t*>(&h);
}
__device__ __forceinline__ ull bcast2(float v) {
    ull r;
    asm("mov.b64 %0, {%1, %1};" : "=l"(r) : "f"(v));
    return r;
}
__device__ __forceinline__ void unpack2(ull v, float& lo, float& hi) {
    asm("mov.b64 {%0, %1}, %2;" : "=f"(lo), "=f"(hi) : "l"(v));
}
__device__ __forceinline__ void fma2(ull& d, ull a, ull b) {
    asm("fma.rn.f32x2 %0, %1, %2, %0;" : "+l"(d) : "l"(a), "l"(b));
}
__device__ __forceinline__ uint32_t smem_u32p(const void* p) {
    uint32_t a;
    asm("{ .reg .u64 t; cvta.to.shared.u64 t, %1; cvt.u32.u64 %0, t; }" : "=r"(a) : "l"(p));
    return a;
}
__device__ __forceinline__ void cp16(uint32_t dst, const void* src) {
    asm volatile("cp.async.cg.shared.global [%0], [%1], 16;" :: "r"(dst), "l"(src));
}
__device__ __forceinline__ void cp_commit() { asm volatile("cp.async.commit_group;"); }
__device__ __forceinline__ void cp_wait0()  { asm volatile("cp.async.wait_group 0;"); }

// m16n8k16 f16 MMA, f32 accumulate
__device__ __forceinline__ void mma_f16(float (&d)[4], const uint32_t (&a)[4],
                                        uint32_t b0, uint32_t b1) {
    asm volatile(
        "mma.sync.aligned.m16n8k16.row.col.f32.f16.f16.f32 "
        "{%0,%1,%2,%3}, {%4,%5,%6,%7}, {%8,%9}, {%0,%1,%2,%3};"
        : "+f"(d[0]), "+f"(d[1]), "+f"(d[2]), "+f"(d[3])
        : "r"(a[0]), "r"(a[1]), "r"(a[2]), "r"(a[3]), "r"(b0), "r"(b1));
}

// ---------------------------------------------------------------------------
// Prep kernel: one block per 64-row stripe (grid = (N/64, B), one wave).
// Stages val once; q/k projection with W from smem (FFMA2, bit-identical math
// to round 10); vt pack from the same staged v. All outputs kslot-permuted.
// ---------------------------------------------------------------------------
__global__ void __launch_bounds__(THREADS) prep_kernel(const float* __restrict__ val,
                                                       const float* __restrict__ Wq,
                                                       const float* __restrict__ Wk) {
    extern __shared__ float ps[];
    const uint32_t sbase = smem_u32p(ps);

    const int b  = blockIdx.y;
    const int n0 = blockIdx.x * TM;
    const int t  = threadIdx.x;

    // ---- stage v rows [n0, n0+64): 64 x 256 fp32, stride 260
    {
        const float* srcv = val + ((size_t)b * N + n0) * D;
#pragma unroll
        for (int it = 0; it < 8; ++it) {
            int p = t + it * THREADS;        // 4096 float4
            int row = p >> 6, c4 = p & 63;
            cp16(sbase + (uint32_t)(PVS + row * 260 + 4 * c4) * 4u, srcv + 4 * p);
        }
        cp_commit();
    }
    // ---- stage W chunk 0 (d = 0..127, both matrices; contiguous 32KB each)
    {
#pragma unroll
        for (int it = 0; it < 4; ++it) {
            int p = t + it * THREADS;        // 2048 float4
            cp16(sbase + (uint32_t)(PWQ + 4 * p) * 4u, Wq + 4 * p);
        }
#pragma unroll
        for (int it = 0; it < 4; ++it) {
            int p = t + it * THREADS;
            cp16(sbase + (uint32_t)(PWK + 4 * p) * 4u, Wk + 4 * p);
        }
        cp_commit();
    }
    cp_wait0();
    __syncthreads();

    // ---- q/k projection: col pair cp = t&31, rows rg*4..rg*4+3 (rg = t>>5)
    const int cpair = t & 31;
    const int rg = t >> 5;

    ull aq[4], ak[4];
#pragma unroll
    for (int j = 0; j < 4; ++j) { aq[j] = 0ull; ak[j] = 0ull; }

#pragma unroll 1
    for (int c = 0; c < 2; ++c) {
        if (c == 1) {
            __syncthreads();                 // all warps done with chunk 0
#pragma unroll
            for (int it = 0; it < 4; ++it) {
                int p = t + it * THREADS;
                cp16(sbase + (uint32_t)(PWQ + 4 * p) * 4u, Wq + 128 * 64 + 4 * p);
            }
#pragma unroll
            for (int it = 0; it < 4; ++it) {
                int p = t + it * THREADS;
                cp16(sbase + (uint32_t)(PWK + 4 * p) * 4u, Wk + 128 * 64 + 4 * p);
            }
            cp_commit();
            cp_wait0();
            __syncthreads();
        }
        const int gd0 = c * 128;
#pragma unroll 4
        for (int d = 0; d < 128; ++d) {
            ull wq2 = *reinterpret_cast<const ull*>(&ps[PWQ + d * 64 + 2 * cpair]);
            ull wk2 = *reinterpret_cast<const ull*>(&ps[PWK + d * 64 + 2 * cpair]);
#pragma unroll
            for (int j = 0; j < 4; ++j) {
                ull vb = bcast2(ps[PVS + (rg * 4 + j) * 260 + gd0 + d]);
                fma2(aq[j], vb, wq2);
                fma2(ak[j], vb, wk2);
            }
        }
    }

    {
        const int slot = kslot(cpair);
#pragma unroll
        for (int j = 0; j < 4; ++j) {
            const size_t base = ((size_t)b * N + n0 + rg * 4 + j) * 32;
            float lo, hi;
            unpack2(aq[j], lo, hi);
            g_q[base + slot] = pack_h2(lo, hi);
            unpack2(ak[j], lo, hi);
            g_k[base + slot] = pack_h2(lo, hi);
        }
    }

    // ---- vt pack: g_vt[b][d][m-pair slot], permuted (same layout as R10)
    {
        uint32_t* gvt_b = g_vt + (size_t)b * D * (N / 2);
#pragma unroll
        for (int it = 0; it < 8; ++it) {
            int p = t + it * THREADS;        // 4096 uint2 outputs
            int drow = p >> 4, j = p & 15;
            int grp = j >> 2, jj = j & 3;
            int mb = grp * 16;
            uint2 o;
            o.x = pack_h2(ps[PVS + (mb + 2 * jj) * 260 + drow],
                          ps[PVS + (mb + 2 * jj + 1) * 260 + drow]);
            o.y = pack_h2(ps[PVS + (mb + 2 * jj + 8) * 260 + drow],
                          ps[PVS + (mb + 2 * jj + 9) * 260 + drow]);
            *reinterpret_cast<uint2*>(
                &gvt_b[(size_t)drow * (N / 2) + n0 / 2 + 2 * j]) = o;
        }
    }
}

// ---------------------------------------------------------------------------
// Kernel 2: fused scores -> softsign -> (edges@state, edges@val), fp16 MMA.
// (round-10 prop body, verbatim — best measured)
// ---------------------------------------------------------------------------
__global__ void __launch_bounds__(THREADS) prop_kernel(const float* __restrict__ state,
                                                       float* __restrict__ out_ds,
                                                       float* __restrict__ out_dv) {
    extern __shared__ float smf[];
    uint32_t* sm = reinterpret_cast<uint32_t*>(smf);
    const uint32_t sbase = smem_u32p(smf);

    const int b  = blockIdx.y;
    const int n0 = blockIdx.x * TM;
    const int t  = threadIdx.x;
    const int wid = t >> 5, lane = t & 31;
    const int g = lane >> 2, tg = lane & 3;
    const int wr = wid & 3, wc = wid >> 2;

    const uint32_t* gk_b  = g_k + (size_t)b * N * 32;
    const uint32_t* gvt_b = g_vt + (size_t)b * D * (N / 2);
    const float* st_b = state + (size_t)b * N;

    auto prefetch = [&](int m0, int buf) {
        const int ofk  = buf ? OFK1 : OFK0;
        const int ofv  = buf ? OFV1 : OFV0;
        const int ofst = buf ? OFST1 : OFST0;
        {   // K tile: 64 rows x 8 uint4
            int row = t >> 3, cc = t & 7;
            cp16(sbase + (uint32_t)(ofk + row * 40 + 4 * cc) * 4u,
                 gk_b + (size_t)(m0 + row) * 32 + 4 * cc);
        }
#pragma unroll
        for (int it = 0; it < 4; ++it) {   // VT: 256 rows x 8 uint4
            int p = t + it * THREADS;
            int row = p >> 3, cc = p & 7;
            cp16(sbase + (uint32_t)(ofv + row * 40 + 4 * cc) * 4u,
                 gvt_b + (size_t)row * (N / 2) + m0 / 2 + 4 * cc);
        }
        if (t < 16)
            cp16(sbase + (uint32_t)(ofst + 4 * t) * 4u, st_b + m0 + 4 * t);
    };

    prefetch(0, 0);
    cp_commit();

    // ---- Q A-fragments from permuted global (one-time): 4 k16-steps
    uint32_t aq[4][4];
    {
        const uint32_t* q0 = g_q + ((size_t)b * N + n0 + 16 * wr + g) * 32;
        const uint32_t* q1 = q0 + 8 * 32;
#pragma unroll
        for (int ks = 0; ks < 4; ++ks) {
            uint2 u0 = *reinterpret_cast<const uint2*>(&q0[8 * ks + 2 * tg]);
            uint2 u1 = *reinterpret_cast<const uint2*>(&q1[8 * ks + 2 * tg]);
            aq[ks][0] = u0.x; aq[ks][1] = u1.x; aq[ks][2] = u0.y; aq[ks][3] = u1.y;
        }
    }

    const int eslot0 = kslot(8 * wc + tg);
    const int eslot1 = kslot(8 * wc + 4 + tg);

    float dv[8][4];
#pragma unroll
    for (int nt = 0; nt < 8; ++nt)
#pragma unroll
        for (int j = 0; j < 4; ++j) dv[nt][j] = 0.f;
    float ds0 = 0.f, ds1 = 0.f;

#pragma unroll 1
    for (int i = 0; i < N / TN; ++i) {
        const int buf = i & 1;
        const int ofk  = buf ? OFK1 : OFK0;
        const int ofv  = buf ? OFV1 : OFV0;
        const int ofst = buf ? OFST1 : OFST0;

        cp_wait0();
        __syncthreads();

        if (i + 1 < N / TN) {
            prefetch((i + 1) * TN, buf ^ 1);
            cp_commit();
        }

        // ---- MMA1: S(16x16 per warp) = Q . K^T  (R=64 -> 4 k16 steps, 2 n8)
        float sacc[2][4];
#pragma unroll
        for (int nt = 0; nt < 2; ++nt)
#pragma unroll
            for (int j = 0; j < 4; ++j) sacc[nt][j] = 0.f;

#pragma unroll
        for (int ks = 0; ks < 4; ++ks) {
#pragma unroll
            for (int nt = 0; nt < 2; ++nt) {
                uint2 bb = *reinterpret_cast<const uint2*>(
                    &sm[ofk + (16 * wc + 8 * nt + g) * 40 + 8 * ks + 2 * tg]);
                mma_f16(sacc[nt], aq[ks], bb.x, bb.y);
            }
        }

        // ---- softsign + delta_state + E(fp16 pairs, permuted slots)
#pragma unroll
        for (int nt = 0; nt < 2; ++nt) {
            const int c0 = 16 * wc + 8 * nt + 2 * tg;
            float e00 = __fdividef(sacc[nt][0], 1.f + fabsf(sacc[nt][0]));
            float e01 = __fdividef(sacc[nt][1], 1.f + fabsf(sacc[nt][1]));
            float e10 = __fdividef(sacc[nt][2], 1.f + fabsf(sacc[nt][2]));
            float e11 = __fdividef(sacc[nt][3], 1.f + fabsf(sacc[nt][3]));
            float s0 = smf[ofst + c0], s1 = smf[ofst + c0 + 1];
            ds0 = fmaf(e00, s0, fmaf(e01, s1, ds0));
            ds1 = fmaf(e10, s0, fmaf(e11, s1, ds1));
            const int es = nt ? eslot1 : eslot0;
            sm[OFE + (16 * wr + g) * 40 + es]     = pack_h2(e00, e01);
            sm[OFE + (16 * wr + g + 8) * 40 + es] = pack_h2(e10, e11);
        }
        __syncthreads();

        // ---- MMA2: DV(16x64 per warp) += E . V  (k=64 -> 4 k16 steps)
#pragma unroll
        for (int ks = 0; ks < 4; ++ks) {
            uint2 A0 = *reinterpret_cast<const uint2*>(
                &sm[OFE + (16 * wr + g) * 40 + 8 * ks + 2 * tg]);
            uint2 A1 = *reinterpret_cast<const uint2*>(
                &sm[OFE + (16 * wr + g + 8) * 40 + 8 * ks + 2 * tg]);
            uint32_t a[4] = {A0.x, A1.x, A0.y, A1.y};
#pragma unroll
            for (int nt = 0; nt < 8; ++nt) {
                uint2 bb = *reinterpret_cast<const uint2*>(
                    &sm[ofv + (64 * wc + 8 * nt + g) * 40 + 8 * ks + 2 * tg]);
                mma_f16(dv[nt], a, bb.x, bb.y);
            }
        }
    }

    // ---- epilogue: DV writes
    {
        const int rowA = n0 + 16 * wr + g;
        float* dA = out_dv + ((size_t)b * N + rowA) * D;
        float* dB = dA + 8 * D;
#pragma unroll
        for (int nt = 0; nt < 8; ++nt) {
            const int col = 64 * wc + 8 * nt + 2 * tg;
            *reinterpret_cast<float2*>(dA + col) = make_float2(dv[nt][0], dv[nt][1]);
            *reinterpret_cast<float2*>(dB + col) = make_float2(dv[nt][2], dv[nt][3]);
        }
    }

    // ---- delta_state reduction (quad shuffle, then 4 wc-partials per row)
    ds0 += __shfl_xor_sync(0xFFFFFFFF, ds0, 1);
    ds0 += __shfl_xor_sync(0xFFFFFFFF, ds0, 2);
    ds1 += __shfl_xor_sync(0xFFFFFFFF, ds1, 1);
    ds1 += __shfl_xor_sync(0xFFFFFFFF, ds1, 2);
    __syncthreads();
    if (tg == 0) {
        smf[OFRD + (16 * wr + g) * 4 + wc]     = ds0;
        smf[OFRD + (16 * wr + g + 8) * 4 + wc] = ds1;
    }
    __syncthreads();
    if (t < TM)
        out_ds[b * N + n0 + t] = (smf[OFRD + t * 4] + smf[OFRD + t * 4 + 1]) +
                                 (smf[OFRD + t * 4 + 2] + smf[OFRD + t * 4 + 3]);
}

}  // namespace

extern "C" void kernel_launch(void* const* d_in, const int* in_sizes, int n_in,
                              void* d_out, int out_size) {
    const float* state = (const float*)d_in[0];   // [B, N]
    const float* val   = (const float*)d_in[1];   // [B, N, D]
    const float* Wq    = (const float*)d_in[2];   // [D, R]
    const float* Wk    = (const float*)d_in[3];   // [D, R]

    float* out_ds = (float*)d_out;                // [B, N]
    float* out_dv = out_ds + B * N;               // [B, N, D]

    cudaFuncSetAttribute(prep_kernel, cudaFuncAttributeMaxDynamicSharedMemorySize, PREP_SMEM);
    cudaFuncSetAttribute(prop_kernel, cudaFuncAttributeMaxDynamicSharedMemorySize, SMEM_BYTES);

    prep_kernel<<<dim3(N / TM, B), THREADS, PREP_SMEM>>>(val, Wq, Wk);
    prop_kernel<<<dim3(N / TM, B), THREADS, SMEM_BYTES>>>(state, out_ds, out_dv);
}

// round 16
// speedup vs baseline: 1.2701x; 1.0197x over previous
#include <cuda_runtime.h>
#include <cuda_fp16.h>
#include <cstdint>

namespace {

constexpr int B = 2, N = 4096, D = 256, R = 64;
constexpr int TM = 64;         // n-rows per block
constexpr int TN = 64;         // m-tile
constexpr int THREADS = 512;   // 16 warps

// ---- prop smem layout in uint32 units; stride 36 (mod 32 == 4): ldmatrix
// 8-row address sets cover 32 distinct banks.
constexpr int STR = 36;
constexpr int OFE   = 0;                     // 64 x 36
constexpr int OFK0  = OFE + 64 * STR;        // 64 x 36
constexpr int OFK1  = OFK0 + 64 * STR;
constexpr int OFV0  = OFK1 + 64 * STR;       // 256 x 36
constexpr int OFV1  = OFV0 + 256 * STR;
constexpr int OFST0 = OFV1 + 256 * STR;      // 64 (floats)
constexpr int OFST1 = OFST0 + 64;
constexpr int OFRD  = OFST1 + 64;            // 512 (floats)
constexpr int SMEM_U32 = OFRD + 512;
constexpr int SMEM_BYTES = SMEM_U32 * 4;     // ~104 KB

// ---- prep smem layout (floats)
constexpr int PVS  = 0;                      // 64 rows x 260 (val, fp32)
constexpr int PWQ  = PVS + 64 * 260;         // 128 x 64
constexpr int PWK  = PWQ + 128 * 64;         // 128 x 64
constexpr int PREP_FLOATS = PWK + 128 * 64;
constexpr int PREP_SMEM = PREP_FLOATS * 4;   // 132096 B

// fp16 pair-packed globals, NATURAL pair order (uint32 = half2)
__device__ uint32_t g_q[B * N * (R / 2)];
__device__ uint32_t g_k[B * N * (R / 2)];
__device__ uint32_t g_vt[B * D * (N / 2)];   // [b][d][m-pair]

typedef unsigned long long ull;

__device__ __forceinline__ uint32_t pack_h2(float lo, float hi) {
    __half2 h = __floats2half2_rn(lo, hi);
    return *reinterpret_cast<uint32_t*>(&h);
}
__device__ __forceinline__ ull bcast2(float v) {
    ull r;
    asm("mov.b64 %0, {%1, %1};" : "=l"(r) : "f"(v));
    return r;
}
__device__ __forceinline__ void unpack2(ull v, float& lo, float& hi) {
    asm("mov.b64 {%0, %1}, %2;" : "=f"(lo), "=f"(hi) : "l"(v));
}
__device__ __forceinline__ void fma2(ull& d, ull a, ull b) {
    asm("fma.rn.f32x2 %0, %1, %2, %0;" : "+l"(d) : "l"(a), "l"(b));
}
__device__ __forceinline__ uint32_t smem_u32p(const void* p) {
    uint32_t a;
    asm("{ .reg .u64 t; cvta.to.shared.u64 t, %1; cvt.u32.u64 %0, t; }" : "=r"(a) : "l"(p));
    return a;
}
__device__ __forceinline__ void cp16(uint32_t dst, const void* src) {
    asm volatile("cp.async.cg.shared.global [%0], [%1], 16;" :: "r"(dst), "l"(src));
}
__device__ __forceinline__ void cp_commit() { asm volatile("cp.async.commit_group;"); }
__device__ __forceinline__ void cp_wait0()  { asm volatile("cp.async.wait_group 0;"); }

__device__ __forceinline__ void ldsm2(uint32_t& r0, uint32_t& r1, uint32_t addr) {
    asm volatile("ldmatrix.sync.aligned.m8n8.x2.shared.b16 {%0,%1}, [%2];"
                 : "=r"(r0), "=r"(r1) : "r"(addr));
}
__device__ __forceinline__ void ldsm4(uint32_t& r0, uint32_t& r1, uint32_t& r2,
                                      uint32_t& r3, uint32_t addr) {
    asm volatile("ldmatrix.sync.aligned.m8n8.x4.shared.b16 {%0,%1,%2,%3}, [%4];"
                 : "=r"(r0), "=r"(r1), "=r"(r2), "=r"(r3) : "r"(addr));
}
__device__ __forceinline__ void mma_f16(float (&d)[4], const uint32_t (&a)[4],
                                        uint32_t b0, uint32_t b1) {
    asm volatile(
        "mma.sync.aligned.m16n8k16.row.col.f32.f16.f16.f32 "
        "{%0,%1,%2,%3}, {%4,%5,%6,%7}, {%8,%9}, {%0,%1,%2,%3};"
        : "+f"(d[0]), "+f"(d[1]), "+f"(d[2]), "+f"(d[3])
        : "r"(a[0]), "r"(a[1]), "r"(a[2]), "r"(a[3]), "r"(b0), "r"(b1));
}

// ---------------------------------------------------------------------------
// Prep kernel (R15 structure; outputs in NATURAL pair order).
// ---------------------------------------------------------------------------
__global__ void __launch_bounds__(THREADS) prep_kernel(const float* __restrict__ val,
                                                       const float* __restrict__ Wq,
                                                       const float* __restrict__ Wk) {
    extern __shared__ float ps[];
    const uint32_t sbase = smem_u32p(ps);

    const int b  = blockIdx.y;
    const int n0 = blockIdx.x * TM;
    const int t  = threadIdx.x;

    {
        const float* srcv = val + ((size_t)b * N + n0) * D;
#pragma unroll
        for (int it = 0; it < 8; ++it) {
            int p = t + it * THREADS;
            int row = p >> 6, c4 = p & 63;
            cp16(sbase + (uint32_t)(PVS + row * 260 + 4 * c4) * 4u, srcv + 4 * p);
        }
        cp_commit();
    }
    {
#pragma unroll
        for (int it = 0; it < 4; ++it) {
            int p = t + it * THREADS;
            cp16(sbase + (uint32_t)(PWQ + 4 * p) * 4u, Wq + 4 * p);
        }
#pragma unroll
        for (int it = 0; it < 4; ++it) {
            int p = t + it * THREADS;
            cp16(sbase + (uint32_t)(PWK + 4 * p) * 4u, Wk + 4 * p);
        }
        cp_commit();
    }
    cp_wait0();
    __syncthreads();

    const int cpair = t & 31;
    const int rg = t >> 5;

    ull aq[4], ak[4];
#pragma unroll
    for (int j = 0; j < 4; ++j) { aq[j] = 0ull; ak[j] = 0ull; }

#pragma unroll 1
    for (int c = 0; c < 2; ++c) {
        if (c == 1) {
            __syncthreads();
#pragma unroll
            for (int it = 0; it < 4; ++it) {
                int p = t + it * THREADS;
                cp16(sbase + (uint32_t)(PWQ + 4 * p) * 4u, Wq + 128 * 64 + 4 * p);
            }
#pragma unroll
            for (int it = 0; it < 4; ++it) {
                int p = t + it * THREADS;
                cp16(sbase + (uint32_t)(PWK + 4 * p) * 4u, Wk + 128 * 64 + 4 * p);
            }
            cp_commit();
            cp_wait0();
            __syncthreads();
        }
        const int gd0 = c * 128;
#pragma unroll 4
        for (int d = 0; d < 128; ++d) {
            ull wq2 = *reinterpret_cast<const ull*>(&ps[PWQ + d * 64 + 2 * cpair]);
            ull wk2 = *reinterpret_cast<const ull*>(&ps[PWK + d * 64 + 2 * cpair]);
#pragma unroll
            for (int j = 0; j < 4; ++j) {
                ull vb = bcast2(ps[PVS + (rg * 4 + j) * 260 + gd0 + d]);
                fma2(aq[j], vb, wq2);
                fma2(ak[j], vb, wk2);
            }
        }
    }

#pragma unroll
    for (int j = 0; j < 4; ++j) {
        const size_t base = ((size_t)b * N + n0 + rg * 4 + j) * 32;
        float lo, hi;
        unpack2(aq[j], lo, hi);
        g_q[base + cpair] = pack_h2(lo, hi);
        unpack2(ak[j], lo, hi);
        g_k[base + cpair] = pack_h2(lo, hi);
    }

    // vt pack, natural pair order
    {
        uint32_t* gvt_b = g_vt + (size_t)b * D * (N / 2);
#pragma unroll
        for (int it = 0; it < 8; ++it) {
            int p = t + it * THREADS;
            int drow = p >> 4, j = p & 15;
            uint2 o;
            o.x = pack_h2(ps[PVS + (4 * j + 0) * 260 + drow],
                          ps[PVS + (4 * j + 1) * 260 + drow]);
            o.y = pack_h2(ps[PVS + (4 * j + 2) * 260 + drow],
                          ps[PVS + (4 * j + 3) * 260 + drow]);
            *reinterpret_cast<uint2*>(
                &gvt_b[(size_t)drow * (N / 2) + n0 / 2 + 2 * j]) = o;
        }
    }
}

// ---------------------------------------------------------------------------
// Prop kernel: 32x8 MMA1 warp tiles, 32x32 MMA2 warp tiles (min fragment
// bytes), ldmatrix everywhere, R10 2-barrier loop structure.
// ---------------------------------------------------------------------------
__global__ void __launch_bounds__(THREADS) prop_kernel(const float* __restrict__ state,
                                                       float* __restrict__ out_ds,
                                                       float* __restrict__ out_dv) {
    extern __shared__ float smf[];
    uint32_t* sm = reinterpret_cast<uint32_t*>(smf);
    const uint32_t sbase = smem_u32p(smf);

    const int b  = blockIdx.y;
    const int n0 = blockIdx.x * TM;
    const int t  = threadIdx.x;
    const int wid = t >> 5, lane = t & 31;
    const int g = lane >> 2, tg = lane & 3;
    const int wr = wid & 1;          // 32-row group (both MMAs)
    const int wc = wid >> 1;         // 0..7: MMA1 8-col group / MMA2 32-dcol group

    const uint32_t* gk_b  = g_k + (size_t)b * N * 32;
    const uint32_t* gvt_b = g_vt + (size_t)b * D * (N / 2);
    const float* st_b = state + (size_t)b * N;

    auto prefetch = [&](int m0, int buf) {
        const int ofk  = buf ? OFK1 : OFK0;
        const int ofv  = buf ? OFV1 : OFV0;
        const int ofst = buf ? OFST1 : OFST0;
        {   // K tile: 64 rows x 8 uint4
            int row = t >> 3, cc = t & 7;
            cp16(sbase + (uint32_t)(ofk + row * STR + 4 * cc) * 4u,
                 gk_b + (size_t)(m0 + row) * 32 + 4 * cc);
        }
#pragma unroll
        for (int it = 0; it < 4; ++it) {   // VT: 256 rows x 8 uint4
            int p = t + it * THREADS;
            int row = p >> 3, cc = p & 7;
            cp16(sbase + (uint32_t)(ofv + row * STR + 4 * cc) * 4u,
                 gvt_b + (size_t)row * (N / 2) + m0 / 2 + 4 * cc);
        }
        if (t < 16)
            cp16(sbase + (uint32_t)(ofst + 4 * t) * 4u, st_b + m0 + 4 * t);
    };

    prefetch(0, 0);
    cp_commit();

    // ---- Q A-fragments (2 rowsets x 4 k16-steps), natural-order global
    uint32_t aq[2][4][4];
#pragma unroll
    for (int s = 0; s < 2; ++s) {
        const uint32_t* q0 = g_q + ((size_t)b * N + n0 + 32 * wr + 16 * s + g) * 32;
        const uint32_t* q1 = q0 + 8 * 32;
#pragma unroll
        for (int ks = 0; ks < 4; ++ks) {
            aq[s][ks][0] = q0[8 * ks + tg];
            aq[s][ks][1] = q1[8 * ks + tg];
            aq[s][ks][2] = q0[8 * ks + tg + 4];
            aq[s][ks][3] = q1[8 * ks + tg + 4];
        }
    }

    // ldmatrix address components
    const int lrow = lane & 7;
    // MMA1 B (K tile), x2: rows 8wc..8wc+8, kb = (lane>>3)&1
    const int b1row = 8 * wc + lrow;
    const int b1kb  = (lane >> 3) & 1;
    // MMA2 A (E tile), x4 per rowset s: row = 32wr + 16s + 8*((lane>>3)&1) + lrow
    const int earow0 = 32 * wr + 8 * ((lane >> 3) & 1) + lrow;
    const int eakb   = lane >> 4;
    // MMA2 B (VT tile), x4 per group u: row = 32wc + 16u + 8*(lane>>4) + lrow
    const int b2row0 = 32 * wc + 8 * (lane >> 4) + lrow;
    const int b2kb   = (lane >> 3) & 1;

    float dv[2][4][4];               // [rowset s][d-n8 tile][frag]
#pragma unroll
    for (int s = 0; s < 2; ++s)
#pragma unroll
        for (int nt = 0; nt < 4; ++nt)
#pragma unroll
            for (int j = 0; j < 4; ++j) dv[s][nt][j] = 0.f;
    float ds[2][2] = {{0.f, 0.f}, {0.f, 0.f}};   // [rowset s][half g/g+8]

#pragma unroll 1
    for (int i = 0; i < N / TN; ++i) {
        const int buf = i & 1;
        const int ofk  = buf ? OFK1 : OFK0;
        const int ofv  = buf ? OFV1 : OFV0;
        const int ofst = buf ? OFST1 : OFST0;

        cp_wait0();
        __syncthreads();

        if (i + 1 < N / TN) {
            prefetch((i + 1) * TN, buf ^ 1);
            cp_commit();
        }

        // ---- MMA1: S(32x8 per warp) = Q . K^T
        float sacc[2][4];
#pragma unroll
        for (int s = 0; s < 2; ++s)
#pragma unroll
            for (int j = 0; j < 4; ++j) sacc[s][j] = 0.f;

#pragma unroll
        for (int ks = 0; ks < 4; ++ks) {
            uint32_t kb0, kb1;
            ldsm2(kb0, kb1,
                  sbase + (uint32_t)(ofk + b1row * STR + 8 * ks + 4 * b1kb) * 4u);
            mma_f16(sacc[0], aq[0][ks], kb0, kb1);
            mma_f16(sacc[1], aq[1][ks], kb0, kb1);
        }

        // ---- softsign + delta_state + E (natural pair cols)
#pragma unroll
        for (int s = 0; s < 2; ++s) {
            const int c0 = 8 * wc + 2 * tg;
            float e00 = __fdividef(sacc[s][0], 1.f + fabsf(sacc[s][0]));
            float e01 = __fdividef(sacc[s][1], 1.f + fabsf(sacc[s][1]));
            float e10 = __fdividef(sacc[s][2], 1.f + fabsf(sacc[s][2]));
            float e11 = __fdividef(sacc[s][3], 1.f + fabsf(sacc[s][3]));
            float s0 = smf[ofst + c0], s1 = smf[ofst + c0 + 1];
            ds[s][0] = fmaf(e00, s0, fmaf(e01, s1, ds[s][0]));
            ds[s][1] = fmaf(e10, s0, fmaf(e11, s1, ds[s][1]));
            const int es = 4 * wc + tg;
            const int er = 32 * wr + 16 * s + g;
            sm[OFE + er * STR + es]       = pack_h2(e00, e01);
            sm[OFE + (er + 8) * STR + es] = pack_h2(e10, e11);
        }
        __syncthreads();

        // ---- MMA2: DV(32x32 per warp) += E . V
#pragma unroll
        for (int ks = 0; ks < 4; ++ks) {
            uint32_t a0[4], a1[4];
            ldsm4(a0[0], a0[1], a0[2], a0[3],
                  sbase + (uint32_t)(OFE + earow0 * STR + 8 * ks + 4 * eakb) * 4u);
            ldsm4(a1[0], a1[1], a1[2], a1[3],
                  sbase + (uint32_t)(OFE + (earow0 + 16) * STR + 8 * ks + 4 * eakb) * 4u);
#pragma unroll
            for (int u = 0; u < 2; ++u) {
                uint32_t v0, v1, v2, v3;
                ldsm4(v0, v1, v2, v3,
                      sbase + (uint32_t)(ofv + (b2row0 + 16 * u) * STR
                                         + 8 * ks + 4 * b2kb) * 4u);
                mma_f16(dv[0][2 * u],     a0, v0, v1);
                mma_f16(dv[0][2 * u + 1], a0, v2, v3);
                mma_f16(dv[1][2 * u],     a1, v0, v1);
                mma_f16(dv[1][2 * u + 1], a1, v2, v3);
            }
        }
    }

    // ---- epilogue: DV writes
#pragma unroll
    for (int s = 0; s < 2; ++s) {
        const int rowA = n0 + 32 * wr + 16 * s + g;
        float* dA = out_dv + ((size_t)b * N + rowA) * D;
        float* dB = dA + 8 * D;
#pragma unroll
        for (int nt = 0; nt < 4; ++nt) {
            const int col = 32 * wc + 8 * nt + 2 * tg;
            *reinterpret_cast<float2*>(dA + col) = make_float2(dv[s][nt][0], dv[s][nt][1]);
            *reinterpret_cast<float2*>(dB + col) = make_float2(dv[s][nt][2], dv[s][nt][3]);
        }
    }

    // ---- delta_state reduction: quad shuffle, then 8 wc-partials per row
#pragma unroll
    for (int s = 0; s < 2; ++s)
#pragma unroll
        for (int h = 0; h < 2; ++h) {
            ds[s][h] += __shfl_xor_sync(0xFFFFFFFF, ds[s][h], 1);
            ds[s][h] += __shfl_xor_sync(0xFFFFFFFF, ds[s][h], 2);
        }
    __syncthreads();
    if (tg == 0) {
#pragma unroll
        for (int s = 0; s < 2; ++s) {
            smf[OFRD + (32 * wr + 16 * s + g) * 8 + wc]     = ds[s][0];
            smf[OFRD + (32 * wr + 16 * s + g + 8) * 8 + wc] = ds[s][1];
        }
    }
    __syncthreads();
    if (t < TM) {
        float r = 0.f;
#pragma unroll
        for (int j = 0; j < 8; ++j) r += smf[OFRD + t * 8 + j];
        out_ds[b * N + n0 + t] = r;
    }
}

}  // namespace

extern "C" void kernel_launch(void* const* d_in, const int* in_sizes, int n_in,
                              void* d_out, int out_size) {
    const float* state = (const float*)d_in[0];   // [B, N]
    const float* val   = (const float*)d_in[1];   // [B, N, D]
    const float* Wq    = (const float*)d_in[2];   // [D, R]
    const float* Wk    = (const float*)d_in[3];   // [D, R]

    float* out_ds = (float*)d_out;                // [B, N]
    float* out_dv = out_ds + B * N;               // [B, N, D]

    cudaFuncSetAttribute(prep_kernel, cudaFuncAttributeMaxDynamicSharedMemorySize, PREP_SMEM);
    cudaFuncSetAttribute(prop_kernel, cudaFuncAttributeMaxDynamicSharedMemorySize, SMEM_BYTES);

    prep_kernel<<<dim3(N / TM, B), THREADS, PREP_SMEM>>>(val, Wq, Wk);
    prop_kernel<<<dim3(N / TM, B), THREADS, SMEM_BYTES>>>(state, out_ds, out_dv);
}